// round 15
// baseline (speedup 1.0000x reference)
#include <cuda_runtime.h>
#include <cuda_fp16.h>
#include <math.h>
#include <stdint.h>

#define NROWS 8192
#define NC    256
#define NWORDS (NC/2)          // 128 uint32 (fp16x2) per row

// ---------------- scratch ----------------------------------------------------
__device__ unsigned g_h16[4][NROWS * NWORDS];  // fp16 packed pairs
__device__ float    g_d1[NROWS];               // v_i . pt_i
__device__ float    g_d2[NROWS];               // t_i . pv_i
__device__ float    g_cs[4][256][NC];          // 32-row column-sum chunks
__device__ float    g_cq[4][256][NC];

// ---------------- small helpers ----------------------------------------------
__device__ __forceinline__ uint32_t smem_u32(const void* p) {
    uint32_t a;
    asm("{ .reg .u64 t; cvta.to.shared.u64 t, %1; cvt.u32.u64 %0, t; }"
        : "=r"(a) : "l"(p));
    return a;
}

#define CP_ASYNC16(dst, src)                                                   \
    asm volatile("cp.async.cg.shared.global [%0], [%1], 16;"                   \
                 :: "r"(dst), "l"(src) : "memory")
#define CP_COMMIT()  asm volatile("cp.async.commit_group;" ::: "memory")
#define CP_WAIT1()   asm volatile("cp.async.wait_group 1;" ::: "memory")

#define LDSM_X4(r0, r1, r2, r3, addr)                                          \
    asm volatile("ldmatrix.sync.aligned.m8n8.x4.shared.b16 {%0,%1,%2,%3}, [%4];" \
                 : "=r"(r0), "=r"(r1), "=r"(r2), "=r"(r3) : "r"(addr))

#define MMA16816(d, a, b0, b1)                                                 \
    asm volatile("mma.sync.aligned.m16n8k16.row.col.f32.f16.f16.f32 "          \
                 "{%0,%1,%2,%3}, {%4,%5,%6,%7}, {%8,%9}, {%0,%1,%2,%3};"       \
                 : "+f"((d)[0]), "+f"((d)[1]), "+f"((d)[2]), "+f"((d)[3])      \
                 : "r"((a)[0]), "r"((a)[1]), "r"((a)[2]), "r"((a)[3]),         \
                   "r"(b0), "r"(b1))

__device__ __forceinline__ unsigned packh2(float a, float b) {
    __half2 h = __floats2half2_rn(a, b);
    return *reinterpret_cast<unsigned*>(&h);
}

// ---------------- 1. fused prep: normalize/pack/colstats/diag + out init -----
// grid 256, block 256 (8 warps x 4 rows = 32-row chunk per block).
__global__ void prep_kernel(const float* __restrict__ v,
                            const float* __restrict__ t,
                            const float* __restrict__ pv,
                            const float* __restrict__ pt,
                            float* __restrict__ out) {
    __shared__ float sm_s[4][NC];
    __shared__ float sm_q[4][NC];

    const int tid  = threadIdx.x;
    const int warp = tid >> 5, lane = tid & 31;
    const float* srcs[4] = { v, t, pv, pt };

    #pragma unroll
    for (int k = 0; k < 4; k++) {
        sm_s[k][tid] = 0.f;  sm_q[k][tid] = 0.f;
    }
    // out init: recall constants + zero mean_rk regions (both sides, 1 elem/thread)
    // per-side pattern: [1s x8192][5s x8192][10s x8192][0s x8192], repeats on t side
    {
        int idx = blockIdx.x * 256 + tid;       // 0..65535
        int r0 = (idx >> 13) & 3;
        float v0 = (r0 == 0) ? 1.f : (r0 == 1) ? 5.f : (r0 == 2) ? 10.f : 0.f;
        out[5 + idx] = v0;
    }
    __syncthreads();

    float s[4][8], q[4][8];
    #pragma unroll
    for (int m = 0; m < 4; m++)
        #pragma unroll
        for (int k = 0; k < 8; k++) { s[m][k] = 0.f; q[m][k] = 0.f; }

    #pragma unroll 2
    for (int rr = 0; rr < 4; rr++) {
        int row = blockIdx.x * 32 + warp * 4 + rr;
        size_t base4 = (size_t)row * (NC / 4);

        float4 x[4][2];
        #pragma unroll
        for (int m = 0; m < 4; m++) {
            const float4* s4 = (const float4*)srcs[m];
            x[m][0] = s4[base4 + lane];
            x[m][1] = s4[base4 + lane + 32];
        }

        float ss[4];
        #pragma unroll
        for (int m = 0; m < 4; m++) {
            ss[m] = x[m][0].x*x[m][0].x + x[m][0].y*x[m][0].y
                  + x[m][0].z*x[m][0].z + x[m][0].w*x[m][0].w
                  + x[m][1].x*x[m][1].x + x[m][1].y*x[m][1].y
                  + x[m][1].z*x[m][1].z + x[m][1].w*x[m][1].w;
        }
        #pragma unroll
        for (int o = 16; o; o >>= 1) {
            #pragma unroll
            for (int m = 0; m < 4; m++)
                ss[m] += __shfl_xor_sync(0xffffffffu, ss[m], o);
        }
        #pragma unroll
        for (int m = 0; m < 4; m++) {
            float r = 1.0f / fmaxf(sqrtf(ss[m]), 1e-12f);
            x[m][0].x *= r; x[m][0].y *= r; x[m][0].z *= r; x[m][0].w *= r;
            x[m][1].x *= r; x[m][1].y *= r; x[m][1].z *= r; x[m][1].w *= r;
        }

        float d1 = x[0][0].x*x[3][0].x + x[0][0].y*x[3][0].y
                 + x[0][0].z*x[3][0].z + x[0][0].w*x[3][0].w
                 + x[0][1].x*x[3][1].x + x[0][1].y*x[3][1].y
                 + x[0][1].z*x[3][1].z + x[0][1].w*x[3][1].w;
        float d2 = x[1][0].x*x[2][0].x + x[1][0].y*x[2][0].y
                 + x[1][0].z*x[2][0].z + x[1][0].w*x[2][0].w
                 + x[1][1].x*x[2][1].x + x[1][1].y*x[2][1].y
                 + x[1][1].z*x[2][1].z + x[1][1].w*x[2][1].w;
        #pragma unroll
        for (int o = 16; o; o >>= 1) {
            d1 += __shfl_xor_sync(0xffffffffu, d1, o);
            d2 += __shfl_xor_sync(0xffffffffu, d2, o);
        }
        if (lane == 0) { g_d1[row] = d1; g_d2[row] = d2; }

        size_t rb = (size_t)row * NWORDS;
        #pragma unroll
        for (int m = 0; m < 4; m++) {
            g_h16[m][rb + 2*lane]      = packh2(x[m][0].x, x[m][0].y);
            g_h16[m][rb + 2*lane + 1]  = packh2(x[m][0].z, x[m][0].w);
            g_h16[m][rb + 64 + 2*lane] = packh2(x[m][1].x, x[m][1].y);
            g_h16[m][rb + 65 + 2*lane] = packh2(x[m][1].z, x[m][1].w);
            float v0 = x[m][0].x, v1 = x[m][0].y, v2 = x[m][0].z, v3 = x[m][0].w;
            float v4 = x[m][1].x, v5 = x[m][1].y, v6 = x[m][1].z, v7 = x[m][1].w;
            s[m][0] += v0; q[m][0] += v0*v0;
            s[m][1] += v1; q[m][1] += v1*v1;
            s[m][2] += v2; q[m][2] += v2*v2;
            s[m][3] += v3; q[m][3] += v3*v3;
            s[m][4] += v4; q[m][4] += v4*v4;
            s[m][5] += v5; q[m][5] += v5*v5;
            s[m][6] += v6; q[m][6] += v6*v6;
            s[m][7] += v7; q[m][7] += v7*v7;
        }
    }

    #pragma unroll
    for (int m = 0; m < 4; m++) {
        #pragma unroll
        for (int k = 0; k < 8; k++) {
            int col = (k < 4) ? (4*lane + k) : (128 + 4*lane + (k - 4));
            atomicAdd(&sm_s[m][col], s[m][k]);
            atomicAdd(&sm_q[m][col], q[m][k]);
        }
    }
    __syncthreads();
    #pragma unroll
    for (int m = 0; m < 4; m++) {
        g_cs[m][blockIdx.x][tid] = sm_s[m][tid];
        g_cq[m][blockIdx.x][tid] = sm_q[m][tid];
    }
}

// ---------------- 2. HMMA GEMM + rank count (frozen champion mainloop) -------
#define A_BYTES  16384
#define B_BYTES  16384
#define STAGE_B  (A_BYTES + B_BYTES)
#define STAGES   3
#define DYN_SMEM (STAGES * STAGE_B + 1024)
#define NCHUNK   4                  // 256 / 64
#define JSPLIT   16
#define NJT      (64 / JSPLIT)      // 4 j-tiles of 128 per CTA
#define TOTAL    (NJT * NCHUNK)

__global__ void __launch_bounds__(128, 2) count_kernel(float* __restrict__ out) {
    extern __shared__ char dynsm[];
    __shared__ int scnt[128];

    const int t = threadIdx.x;
    const int lane = t & 31;
    const int wid = t >> 5;
    const int warp_m = wid & 1;
    const int warp_n = wid >> 1;
    const int mat = blockIdx.y;
    const int i0 = blockIdx.x * 128;
    const int jt0 = blockIdx.z * NJT;

    const unsigned* __restrict__ A = g_h16[mat ? 1 : 0];
    const unsigned* __restrict__ B = g_h16[mat ? 2 : 3];
    const float*    __restrict__ diag = mat ? g_d2 : g_d1;
    float* __restrict__ mrk = out + 5 + (size_t)(mat ? 7 : 3) * NROWS;

    const unsigned sb = (smem_u32(dynsm) + 1023u) & ~1023u;

    if (t < 128) scnt[t] = 0;

    const int lg_r = t >> 3;
    const int lg_q = t & 7;
    const unsigned swq = ((unsigned)(lg_q ^ (lg_r & 7))) << 4;

    float dva[4], dvb[4];
    #pragma unroll
    for (int mt = 0; mt < 4; mt++) {
        int ra = i0 + warp_m * 64 + mt * 16 + (lane >> 2);
        dva[mt] = diag[ra];
        dvb[mt] = diag[ra + 8];
    }
    int cnt[4][2];
    #pragma unroll
    for (int mt = 0; mt < 4; mt++) { cnt[mt][0] = 0; cnt[mt][1] = 0; }

    unsigned offA[4], permA[4];
    #pragma unroll
    for (int mt = 0; mt < 4; mt++) {
        int rowA = warp_m * 64 + mt * 16 + (lane & 15);
        offA[mt] = rowA * 128;
        permA[mt] = (rowA & 7);
    }
    const unsigned halfA = lane >> 4;
    unsigned offB[4], permB[4];
    #pragma unroll
    for (int np = 0; np < 4; np++) {
        int rowB = warp_n * 64 + np * 16 + ((lane & 16) >> 1) + (lane & 7);
        offB[np] = A_BYTES + rowB * 128;
        permB[np] = (rowB & 7);
    }
    const unsigned halfB = (lane >> 3) & 1;

    float acc[4][8][4];
    #pragma unroll
    for (int mt = 0; mt < 4; mt++)
        #pragma unroll
        for (int nt = 0; nt < 8; nt++)
            #pragma unroll
            for (int c = 0; c < 4; c++) acc[mt][nt][c] = 0.f;

    auto issue = [&](int idx) {
        int jt  = idx >> 2;
        int kc  = idx & 3;
        int kbw = kc * 32 + lg_q * 4;
        size_t jb = (size_t)(jt0 + jt) * 128 * NWORDS;
        unsigned st = sb + (unsigned)(idx % STAGES) * STAGE_B;
        #pragma unroll
        for (int h = 0; h < 8; h++) {
            int r = lg_r + h * 16;
            CP_ASYNC16(st + r * 128 + swq,
                       __cvta_generic_to_global(A + (size_t)(i0 + r) * NWORDS + kbw));
            CP_ASYNC16(st + A_BYTES + r * 128 + swq,
                       __cvta_generic_to_global(B + jb + (size_t)r * NWORDS + kbw));
        }
    };

    issue(0); CP_COMMIT();
    issue(1); CP_COMMIT();

    for (int idx = 0; idx < TOTAL; idx++) {
        const int jt = idx >> 2;
        const int kc = idx & 3;

        CP_WAIT1();
        __syncthreads();

        if (idx + 2 < TOTAL) { issue(idx + 2); CP_COMMIT(); }

        const unsigned base = sb + (unsigned)(idx % STAGES) * STAGE_B;
        #pragma unroll
        for (int ks = 0; ks < 4; ks++) {
            unsigned a[4][4], b[4][4];
            #pragma unroll
            for (int mt = 0; mt < 4; mt++) {
                unsigned addr = base + offA[mt] + (((2u*ks + halfA) ^ permA[mt]) << 4);
                LDSM_X4(a[mt][0], a[mt][1], a[mt][2], a[mt][3], addr);
            }
            #pragma unroll
            for (int np = 0; np < 4; np++) {
                unsigned addr = base + offB[np] + (((2u*ks + halfB) ^ permB[np]) << 4);
                LDSM_X4(b[np][0], b[np][1], b[np][2], b[np][3], addr);
            }
            #pragma unroll
            for (int mt = 0; mt < 4; mt++) {
                #pragma unroll
                for (int np = 0; np < 4; np++) {
                    MMA16816(acc[mt][np * 2],     a[mt], b[np][0], b[np][1]);
                    MMA16816(acc[mt][np * 2 + 1], a[mt], b[np][2], b[np][3]);
                }
            }
        }

        if (kc == NCHUNK - 1) {
            int jbase = (jt0 + jt) * 128;
            if (jbase != i0) {
                #pragma unroll
                for (int mt = 0; mt < 4; mt++) {
                    float da = dva[mt], db = dvb[mt];
                    int ca = 0, cb = 0;
                    #pragma unroll
                    for (int nt = 0; nt < 8; nt++) {
                        ca += (acc[mt][nt][0] > da);
                        ca += (acc[mt][nt][1] > da);
                        cb += (acc[mt][nt][2] > db);
                        cb += (acc[mt][nt][3] > db);
                        acc[mt][nt][0] = 0.f; acc[mt][nt][1] = 0.f;
                        acc[mt][nt][2] = 0.f; acc[mt][nt][3] = 0.f;
                    }
                    cnt[mt][0] += ca;
                    cnt[mt][1] += cb;
                }
            } else {
                int j0 = jbase + warp_n * 64 + (lane & 3) * 2;
                #pragma unroll
                for (int mt = 0; mt < 4; mt++) {
                    int ia = i0 + warp_m * 64 + mt * 16 + (lane >> 2);
                    int ib = ia + 8;
                    float da = dva[mt], db = dvb[mt];
                    int ca = 0, cb = 0;
                    #pragma unroll
                    for (int nt = 0; nt < 8; nt++) {
                        int j = j0 + nt * 8;
                        ca += (j     != ia) && (acc[mt][nt][0] > da);
                        ca += (j + 1 != ia) && (acc[mt][nt][1] > da);
                        cb += (j     != ib) && (acc[mt][nt][2] > db);
                        cb += (j + 1 != ib) && (acc[mt][nt][3] > db);
                        acc[mt][nt][0] = 0.f; acc[mt][nt][1] = 0.f;
                        acc[mt][nt][2] = 0.f; acc[mt][nt][3] = 0.f;
                    }
                    cnt[mt][0] += ca;
                    cnt[mt][1] += cb;
                }
            }
        }
    }

    __syncthreads();
    #pragma unroll
    for (int mt = 0; mt < 4; mt++) {
        int la = warp_m * 64 + mt * 16 + (lane >> 2);
        atomicAdd(&scnt[la], cnt[mt][0]);
        atomicAdd(&scnt[la + 8], cnt[mt][1]);
    }
    __syncthreads();
    // integer-valued float adds are exact (counts <= 8191) -> deterministic
    if (t < 128) atomicAdd(&mrk[i0 + t], (float)scnt[t]);
}

// ---------------- 3. scalars (parallel: 5 blocks) ----------------------------
__global__ void finalize_kernel(float* __restrict__ out) {
    __shared__ float red[256];
    int t = threadIdx.x;
    int m = blockIdx.x;

    if (m < 4) {
        float s = 0.f, q = 0.f;
        #pragma unroll 8
        for (int ch = 0; ch < 256; ch++) { s += g_cs[m][ch][t]; q += g_cq[m][ch][t]; }
        float var = (q - s * s / (float)NROWS) / (float)(NROWS - 1);
        red[t] = sqrtf(fmaxf(var, 0.f));
        __syncthreads();
        for (int off = 128; off; off >>= 1) {
            if (t < off) red[t] += red[t + off];
            __syncthreads();
        }
        if (t == 0) out[1 + m] = red[0] / (float)NC;
    } else {
        float s1 = 0.f, s2 = 0.f;
        for (int i = t; i < NROWS; i += 256) { s1 += g_d1[i]; s2 += g_d2[i]; }
        red[t] = s1; __syncthreads();
        for (int off = 128; off; off >>= 1) {
            if (t < off) red[t] += red[t + off];
            __syncthreads();
        }
        float S1 = red[0]; __syncthreads();
        red[t] = s2; __syncthreads();
        for (int off = 128; off; off >>= 1) {
            if (t < off) red[t] += red[t + off];
            __syncthreads();
        }
        if (t == 0) {
            float S2 = red[0];
            out[0] = -0.5f * (S1 / (float)NROWS) - 0.5f * (S2 / (float)NROWS);
        }
    }
}

// ---------------- launch -----------------------------------------------------
extern "C" void kernel_launch(void* const* d_in, const int* in_sizes, int n_in,
                              void* d_out, int out_size) {
    const float* v  = (const float*)d_in[0];
    const float* t  = (const float*)d_in[1];
    const float* pv = (const float*)d_in[2];
    const float* pt = (const float*)d_in[3];
    float* out = (float*)d_out;

    cudaFuncSetAttribute(count_kernel,
                         cudaFuncAttributeMaxDynamicSharedMemorySize, DYN_SMEM);

    prep_kernel<<<256, 256>>>(v, t, pv, pt, out);
    count_kernel<<<dim3(64, 2, JSPLIT), 128, DYN_SMEM>>>(out);
    finalize_kernel<<<5, 256>>>(out);
}

// round 16
// speedup vs baseline: 1.0819x; 1.0819x over previous
#include <cuda_runtime.h>
#include <cuda_fp16.h>
#include <math.h>
#include <stdint.h>

#define NROWS 8192
#define NC    256
#define NWORDS (NC/2)          // 128 uint32 (fp16x2) per row

// ---------------- scratch ----------------------------------------------------
__device__ unsigned g_h16[4][NROWS * NWORDS];  // fp16 packed pairs
__device__ float    g_d1[NROWS];               // v_i . pt_i
__device__ float    g_d2[NROWS];               // t_i . pv_i
__device__ float    g_cs[4][128][NC];          // 64-row column-sum chunks
__device__ float    g_cq[4][128][NC];

// ---------------- small helpers ----------------------------------------------
__device__ __forceinline__ uint32_t smem_u32(const void* p) {
    uint32_t a;
    asm("{ .reg .u64 t; cvta.to.shared.u64 t, %1; cvt.u32.u64 %0, t; }"
        : "=r"(a) : "l"(p));
    return a;
}

#define CP_ASYNC16(dst, src)                                                   \
    asm volatile("cp.async.cg.shared.global [%0], [%1], 16;"                   \
                 :: "r"(dst), "l"(src) : "memory")
#define CP_COMMIT()  asm volatile("cp.async.commit_group;" ::: "memory")
#define CP_WAIT1()   asm volatile("cp.async.wait_group 1;" ::: "memory")
#define CP_WAIT0()   asm volatile("cp.async.wait_group 0;" ::: "memory")

#define LDSM_X4(r0, r1, r2, r3, addr)                                          \
    asm volatile("ldmatrix.sync.aligned.m8n8.x4.shared.b16 {%0,%1,%2,%3}, [%4];" \
                 : "=r"(r0), "=r"(r1), "=r"(r2), "=r"(r3) : "r"(addr))

#define MMA16816(d, a, b0, b1)                                                 \
    asm volatile("mma.sync.aligned.m16n8k16.row.col.f32.f16.f16.f32 "          \
                 "{%0,%1,%2,%3}, {%4,%5,%6,%7}, {%8,%9}, {%0,%1,%2,%3};"       \
                 : "+f"((d)[0]), "+f"((d)[1]), "+f"((d)[2]), "+f"((d)[3])      \
                 : "r"((a)[0]), "r"((a)[1]), "r"((a)[2]), "r"((a)[3]),         \
                   "r"(b0), "r"(b1))

__device__ __forceinline__ unsigned packh2(float a, float b) {
    __half2 h = __floats2half2_rn(a, b);
    return *reinterpret_cast<unsigned*>(&h);
}

// ---------------- 1. fused prep (R14 champion config) ------------------------
// grid 128, block 256 (8 warps x 8 rows = 64-row chunk per block).
__global__ void prep_kernel(const float* __restrict__ v,
                            const float* __restrict__ t,
                            const float* __restrict__ pv,
                            const float* __restrict__ pt,
                            float* __restrict__ out) {
    __shared__ float sm_s[4][NC];
    __shared__ float sm_q[4][NC];

    const int tid  = threadIdx.x;
    const int warp = tid >> 5, lane = tid & 31;
    const float* srcs[4] = { v, t, pv, pt };

    #pragma unroll
    for (int k = 0; k < 4; k++) {
        sm_s[k][tid] = 0.f;  sm_q[k][tid] = 0.f;
    }
    {
        int idx = blockIdx.x * 256 + tid;       // 0..32767
        int r0 = idx >> 13;                     // 0..3
        float v0 = (r0 == 0) ? 1.f : (r0 == 1) ? 5.f : (r0 == 2) ? 10.f : 0.f;
        out[5 + idx] = v0;
        out[5 + 4 * NROWS + idx] = v0;
    }
    __syncthreads();

    float s[4][8], q[4][8];
    #pragma unroll
    for (int m = 0; m < 4; m++)
        #pragma unroll
        for (int k = 0; k < 8; k++) { s[m][k] = 0.f; q[m][k] = 0.f; }

    for (int rr = 0; rr < 8; rr++) {
        int row = blockIdx.x * 64 + warp * 8 + rr;
        size_t base4 = (size_t)row * (NC / 4);

        float4 x[4][2];
        #pragma unroll
        for (int m = 0; m < 4; m++) {
            const float4* s4 = (const float4*)srcs[m];
            x[m][0] = s4[base4 + lane];
            x[m][1] = s4[base4 + lane + 32];
        }

        float ss[4];
        #pragma unroll
        for (int m = 0; m < 4; m++) {
            ss[m] = x[m][0].x*x[m][0].x + x[m][0].y*x[m][0].y
                  + x[m][0].z*x[m][0].z + x[m][0].w*x[m][0].w
                  + x[m][1].x*x[m][1].x + x[m][1].y*x[m][1].y
                  + x[m][1].z*x[m][1].z + x[m][1].w*x[m][1].w;
        }
        #pragma unroll
        for (int o = 16; o; o >>= 1) {
            #pragma unroll
            for (int m = 0; m < 4; m++)
                ss[m] += __shfl_xor_sync(0xffffffffu, ss[m], o);
        }
        #pragma unroll
        for (int m = 0; m < 4; m++) {
            float r = 1.0f / fmaxf(sqrtf(ss[m]), 1e-12f);
            x[m][0].x *= r; x[m][0].y *= r; x[m][0].z *= r; x[m][0].w *= r;
            x[m][1].x *= r; x[m][1].y *= r; x[m][1].z *= r; x[m][1].w *= r;
        }

        float d1 = x[0][0].x*x[3][0].x + x[0][0].y*x[3][0].y
                 + x[0][0].z*x[3][0].z + x[0][0].w*x[3][0].w
                 + x[0][1].x*x[3][1].x + x[0][1].y*x[3][1].y
                 + x[0][1].z*x[3][1].z + x[0][1].w*x[3][1].w;
        float d2 = x[1][0].x*x[2][0].x + x[1][0].y*x[2][0].y
                 + x[1][0].z*x[2][0].z + x[1][0].w*x[2][0].w
                 + x[1][1].x*x[2][1].x + x[1][1].y*x[2][1].y
                 + x[1][1].z*x[2][1].z + x[1][1].w*x[2][1].w;
        #pragma unroll
        for (int o = 16; o; o >>= 1) {
            d1 += __shfl_xor_sync(0xffffffffu, d1, o);
            d2 += __shfl_xor_sync(0xffffffffu, d2, o);
        }
        if (lane == 0) { g_d1[row] = d1; g_d2[row] = d2; }

        size_t rb = (size_t)row * NWORDS;
        #pragma unroll
        for (int m = 0; m < 4; m++) {
            g_h16[m][rb + 2*lane]      = packh2(x[m][0].x, x[m][0].y);
            g_h16[m][rb + 2*lane + 1]  = packh2(x[m][0].z, x[m][0].w);
            g_h16[m][rb + 64 + 2*lane] = packh2(x[m][1].x, x[m][1].y);
            g_h16[m][rb + 65 + 2*lane] = packh2(x[m][1].z, x[m][1].w);
            float v0 = x[m][0].x, v1 = x[m][0].y, v2 = x[m][0].z, v3 = x[m][0].w;
            float v4 = x[m][1].x, v5 = x[m][1].y, v6 = x[m][1].z, v7 = x[m][1].w;
            s[m][0] += v0; q[m][0] += v0*v0;
            s[m][1] += v1; q[m][1] += v1*v1;
            s[m][2] += v2; q[m][2] += v2*v2;
            s[m][3] += v3; q[m][3] += v3*v3;
            s[m][4] += v4; q[m][4] += v4*v4;
            s[m][5] += v5; q[m][5] += v5*v5;
            s[m][6] += v6; q[m][6] += v6*v6;
            s[m][7] += v7; q[m][7] += v7*v7;
        }
    }

    #pragma unroll
    for (int m = 0; m < 4; m++) {
        #pragma unroll
        for (int k = 0; k < 8; k++) {
            int col = (k < 4) ? (4*lane + k) : (128 + 4*lane + (k - 4));
            atomicAdd(&sm_s[m][col], s[m][k]);
            atomicAdd(&sm_q[m][col], q[m][k]);
        }
    }
    __syncthreads();
    #pragma unroll
    for (int m = 0; m < 4; m++) {
        g_cs[m][blockIdx.x][tid] = sm_s[m][tid];
        g_cq[m][blockIdx.x][tid] = sm_q[m][tid];
    }
}

// ---------------- 2. HMMA GEMM + rank count (persistent A) -------------------
// Single-term fp16 GEMM, K=256. BM=BN=128. 128 threads, 4 warps (2x2),
// warp tile 64x64. A (64KB, 4 k-slabs) resident in smem for the whole CTA;
// only B streams through a 2-stage buffer. 2 CTAs/SM, j-range split 16 ways.
#define A_REGION 65536              // 4 slabs x 16KB
#define B_STAGE  16384
#define DYN_SMEM (A_REGION + 2 * B_STAGE + 1024)
#define NCHUNK   4                  // 256 / 64
#define JSPLIT   16
#define NJT      (64 / JSPLIT)      // 4 j-tiles of 128 per CTA
#define TOTAL    (NJT * NCHUNK)

__global__ void __launch_bounds__(128, 2) count_kernel(float* __restrict__ out) {
    extern __shared__ char dynsm[];
    __shared__ int scnt[128];

    const int t = threadIdx.x;
    const int lane = t & 31;
    const int wid = t >> 5;
    const int warp_m = wid & 1;
    const int warp_n = wid >> 1;
    const int mat = blockIdx.y;
    const int i0 = blockIdx.x * 128;
    const int jt0 = blockIdx.z * NJT;

    const unsigned* __restrict__ A = g_h16[mat ? 1 : 0];
    const unsigned* __restrict__ B = g_h16[mat ? 2 : 3];
    const float*    __restrict__ diag = mat ? g_d2 : g_d1;
    float* __restrict__ mrk = out + 5 + (size_t)(mat ? 7 : 3) * NROWS;

    const unsigned sb = (smem_u32(dynsm) + 1023u) & ~1023u;
    const unsigned bbase0 = sb + A_REGION;

    if (t < 128) scnt[t] = 0;

    const int lg_r = t >> 3;
    const int lg_q = t & 7;
    const unsigned swq = ((unsigned)(lg_q ^ (lg_r & 7))) << 4;

    float dva[4], dvb[4];
    #pragma unroll
    for (int mt = 0; mt < 4; mt++) {
        int ra = i0 + warp_m * 64 + mt * 16 + (lane >> 2);
        dva[mt] = diag[ra];
        dvb[mt] = diag[ra + 8];
    }
    int cnt[4][2];
    #pragma unroll
    for (int mt = 0; mt < 4; mt++) { cnt[mt][0] = 0; cnt[mt][1] = 0; }

    unsigned offA[4], permA[4];
    #pragma unroll
    for (int mt = 0; mt < 4; mt++) {
        int rowA = warp_m * 64 + mt * 16 + (lane & 15);
        offA[mt] = rowA * 128;
        permA[mt] = (rowA & 7);
    }
    const unsigned halfA = lane >> 4;
    unsigned offB[4], permB[4];
    #pragma unroll
    for (int np = 0; np < 4; np++) {
        int rowB = warp_n * 64 + np * 16 + ((lane & 16) >> 1) + (lane & 7);
        offB[np] = rowB * 128;
        permB[np] = (rowB & 7);
    }
    const unsigned halfB = (lane >> 3) & 1;

    float acc[4][8][4];
    #pragma unroll
    for (int mt = 0; mt < 4; mt++)
        #pragma unroll
        for (int nt = 0; nt < 8; nt++)
            #pragma unroll
            for (int c = 0; c < 4; c++) acc[mt][nt][c] = 0.f;

    auto issueB = [&](int idx) {
        int jt  = idx >> 2;
        int kc  = idx & 3;
        int kbw = kc * 32 + lg_q * 4;
        size_t jb = (size_t)(jt0 + jt) * 128 * NWORDS;
        unsigned st = bbase0 + (unsigned)(idx & 1) * B_STAGE;
        #pragma unroll
        for (int h = 0; h < 8; h++) {
            int r = lg_r + h * 16;
            CP_ASYNC16(st + r * 128 + swq,
                       __cvta_generic_to_global(B + jb + (size_t)r * NWORDS + kbw));
        }
    };

    // prologue: persistent A (4 slabs) + B0 in group0, B1 in group1
    #pragma unroll
    for (int kc = 0; kc < 4; kc++) {
        int kbw = kc * 32 + lg_q * 4;
        unsigned dst = sb + (unsigned)kc * 16384;
        #pragma unroll
        for (int h = 0; h < 8; h++) {
            int r = lg_r + h * 16;
            CP_ASYNC16(dst + r * 128 + swq,
                       __cvta_generic_to_global(A + (size_t)(i0 + r) * NWORDS + kbw));
        }
    }
    issueB(0); CP_COMMIT();
    issueB(1); CP_COMMIT();

    for (int idx = 0; idx < TOTAL; idx++) {
        const int jt = idx >> 2;
        const int kc = idx & 3;

        if (idx < TOTAL - 1) CP_WAIT1(); else CP_WAIT0();
        __syncthreads();

        const unsigned abase = sb + (unsigned)kc * 16384;
        const unsigned bb = bbase0 + (unsigned)(idx & 1) * B_STAGE;
        #pragma unroll
        for (int ks = 0; ks < 4; ks++) {
            unsigned a[4][4], b[4][4];
            #pragma unroll
            for (int mt = 0; mt < 4; mt++) {
                unsigned addr = abase + offA[mt] + (((2u*ks + halfA) ^ permA[mt]) << 4);
                LDSM_X4(a[mt][0], a[mt][1], a[mt][2], a[mt][3], addr);
            }
            #pragma unroll
            for (int np = 0; np < 4; np++) {
                unsigned addr = bb + offB[np] + (((2u*ks + halfB) ^ permB[np]) << 4);
                LDSM_X4(b[np][0], b[np][1], b[np][2], b[np][3], addr);
            }
            #pragma unroll
            for (int mt = 0; mt < 4; mt++) {
                #pragma unroll
                for (int np = 0; np < 4; np++) {
                    MMA16816(acc[mt][np * 2],     a[mt], b[np][0], b[np][1]);
                    MMA16816(acc[mt][np * 2 + 1], a[mt], b[np][2], b[np][3]);
                }
            }
        }

        if (kc == NCHUNK - 1) {
            int jbase = (jt0 + jt) * 128;
            if (jbase != i0) {
                #pragma unroll
                for (int mt = 0; mt < 4; mt++) {
                    float da = dva[mt], db = dvb[mt];
                    int ca = 0, cb = 0;
                    #pragma unroll
                    for (int nt = 0; nt < 8; nt++) {
                        ca += (acc[mt][nt][0] > da);
                        ca += (acc[mt][nt][1] > da);
                        cb += (acc[mt][nt][2] > db);
                        cb += (acc[mt][nt][3] > db);
                        acc[mt][nt][0] = 0.f; acc[mt][nt][1] = 0.f;
                        acc[mt][nt][2] = 0.f; acc[mt][nt][3] = 0.f;
                    }
                    cnt[mt][0] += ca;
                    cnt[mt][1] += cb;
                }
            } else {
                int j0 = jbase + warp_n * 64 + (lane & 3) * 2;
                #pragma unroll
                for (int mt = 0; mt < 4; mt++) {
                    int ia = i0 + warp_m * 64 + mt * 16 + (lane >> 2);
                    int ib = ia + 8;
                    float da = dva[mt], db = dvb[mt];
                    int ca = 0, cb = 0;
                    #pragma unroll
                    for (int nt = 0; nt < 8; nt++) {
                        int j = j0 + nt * 8;
                        ca += (j     != ia) && (acc[mt][nt][0] > da);
                        ca += (j + 1 != ia) && (acc[mt][nt][1] > da);
                        cb += (j     != ib) && (acc[mt][nt][2] > db);
                        cb += (j + 1 != ib) && (acc[mt][nt][3] > db);
                        acc[mt][nt][0] = 0.f; acc[mt][nt][1] = 0.f;
                        acc[mt][nt][2] = 0.f; acc[mt][nt][3] = 0.f;
                    }
                    cnt[mt][0] += ca;
                    cnt[mt][1] += cb;
                }
            }
        }

        // all warps done reading B stage (idx&1) before it is overwritten
        __syncthreads();
        if (idx + 2 < TOTAL) { issueB(idx + 2); CP_COMMIT(); }
    }

    #pragma unroll
    for (int mt = 0; mt < 4; mt++) {
        int la = warp_m * 64 + mt * 16 + (lane >> 2);
        atomicAdd(&scnt[la], cnt[mt][0]);
        atomicAdd(&scnt[la + 8], cnt[mt][1]);
    }
    __syncthreads();
    // integer-valued float adds are exact (counts <= 8191) -> deterministic
    if (t < 128) atomicAdd(&mrk[i0 + t], (float)scnt[t]);
}

// ---------------- 3. scalars (parallel: 5 blocks) ----------------------------
__global__ void finalize_kernel(float* __restrict__ out) {
    __shared__ float red[256];
    int t = threadIdx.x;
    int m = blockIdx.x;

    if (m < 4) {
        float s = 0.f, q = 0.f;
        #pragma unroll 8
        for (int ch = 0; ch < 128; ch++) { s += g_cs[m][ch][t]; q += g_cq[m][ch][t]; }
        float var = (q - s * s / (float)NROWS) / (float)(NROWS - 1);
        red[t] = sqrtf(fmaxf(var, 0.f));
        __syncthreads();
        for (int off = 128; off; off >>= 1) {
            if (t < off) red[t] += red[t + off];
            __syncthreads();
        }
        if (t == 0) out[1 + m] = red[0] / (float)NC;
    } else {
        float s1 = 0.f, s2 = 0.f;
        for (int i = t; i < NROWS; i += 256) { s1 += g_d1[i]; s2 += g_d2[i]; }
        red[t] = s1; __syncthreads();
        for (int off = 128; off; off >>= 1) {
            if (t < off) red[t] += red[t + off];
            __syncthreads();
        }
        float S1 = red[0]; __syncthreads();
        red[t] = s2; __syncthreads();
        for (int off = 128; off; off >>= 1) {
            if (t < off) red[t] += red[t + off];
            __syncthreads();
        }
        if (t == 0) {
            float S2 = red[0];
            out[0] = -0.5f * (S1 / (float)NROWS) - 0.5f * (S2 / (float)NROWS);
        }
    }
}

// ---------------- launch -----------------------------------------------------
extern "C" void kernel_launch(void* const* d_in, const int* in_sizes, int n_in,
                              void* d_out, int out_size) {
    const float* v  = (const float*)d_in[0];
    const float* t  = (const float*)d_in[1];
    const float* pv = (const float*)d_in[2];
    const float* pt = (const float*)d_in[3];
    float* out = (float*)d_out;

    cudaFuncSetAttribute(count_kernel,
                         cudaFuncAttributeMaxDynamicSharedMemorySize, DYN_SMEM);

    prep_kernel<<<128, 256>>>(v, t, pv, pt, out);
    count_kernel<<<dim3(64, 2, JSPLIT), 128, DYN_SMEM>>>(out);
    finalize_kernel<<<5, 256>>>(out);
}